// round 1
// baseline (speedup 1.0000x reference)
#include <cuda_runtime.h>

#define D_FF     11008
#define D_MODEL  4096
#define REMAINED 4403
#define BATCH    32

#define TILE_N   32      // rows (gathered weight rows) per block
#define THREADS  128     // 16 ty (batch pairs) x 8 tx (row groups)

// Packed fp32x2 FMA (Blackwell): d.lo = a.lo*b.lo + c.lo ; d.hi = a.hi*b.hi + c.hi
__device__ __forceinline__ void ffma2(unsigned long long& acc,
                                      unsigned long long a,
                                      unsigned long long b) {
    asm("fma.rn.f32x2 %0, %1, %2, %0;" : "+l"(acc) : "l"(a), "l"(b));
}

__device__ __forceinline__ float f32x2_hsum(unsigned long long v) {
    unsigned int lo, hi;
    asm("mov.b64 {%0, %1}, %2;" : "=r"(lo), "=r"(hi) : "l"(v));
    return __uint_as_float(lo) + __uint_as_float(hi);
}

__global__ void __launch_bounds__(THREADS, 1)
sparse_rowgather_gemm(const float* __restrict__ x,      // [32, 4096]
                      const float* __restrict__ w,      // [11008, 4096]
                      const int*   __restrict__ idx,    // [4403]
                      float*       __restrict__ out)    // [32, 4403]
{
    const int tid = threadIdx.x;
    const int tx  = tid & 7;     // 0..7  -> row groups
    const int ty  = tid >> 3;    // 0..15 -> batch pairs
    const int m0  = ty << 1;     // batch rows m0, m0+1
    const int nbase = blockIdx.x * TILE_N;

    // Resolve the 4 gathered weight rows this thread owns (n = nbase + tx + 8j)
    int n_idx[4];
    const ulonglong2* wp[4];
#pragma unroll
    for (int j = 0; j < 4; j++) {
        n_idx[j] = nbase + tx + 8 * j;
        int r = (n_idx[j] < REMAINED) ? idx[n_idx[j]] : 0;
        wp[j] = (const ulonglong2*)(w + (size_t)r * D_MODEL);
    }
    const ulonglong2* xp0 = (const ulonglong2*)(x + (size_t)m0 * D_MODEL);
    const ulonglong2* xp1 = (const ulonglong2*)(x + (size_t)(m0 + 1) * D_MODEL);

    // 8 packed accumulators: acc[m][j] holds (sum over even k, sum over odd k)
    unsigned long long acc[2][4];
#pragma unroll
    for (int m = 0; m < 2; m++)
#pragma unroll
        for (int j = 0; j < 4; j++) acc[m][j] = 0ull;

    const int QUADS = D_MODEL / 4;   // 1024 iterations, 4 floats (2 k-pairs) each

    // Software pipeline: prefetch quad q+1 while computing quad q
    ulonglong2 a0 = xp0[0];
    ulonglong2 a1 = xp1[0];
    ulonglong2 b[4];
#pragma unroll
    for (int j = 0; j < 4; j++) b[j] = wp[j][0];

#pragma unroll 2
    for (int q = 0; q < QUADS - 1; q++) {
        ulonglong2 na0 = xp0[q + 1];
        ulonglong2 na1 = xp1[q + 1];
        ulonglong2 nb[4];
#pragma unroll
        for (int j = 0; j < 4; j++) nb[j] = wp[j][q + 1];

#pragma unroll
        for (int j = 0; j < 4; j++) {
            ffma2(acc[0][j], a0.x, b[j].x);
            ffma2(acc[1][j], a1.x, b[j].x);
            ffma2(acc[0][j], a0.y, b[j].y);
            ffma2(acc[1][j], a1.y, b[j].y);
        }

        a0 = na0; a1 = na1;
#pragma unroll
        for (int j = 0; j < 4; j++) b[j] = nb[j];
    }

    // Final quad
#pragma unroll
    for (int j = 0; j < 4; j++) {
        ffma2(acc[0][j], a0.x, b[j].x);
        ffma2(acc[1][j], a1.x, b[j].x);
        ffma2(acc[0][j], a0.y, b[j].y);
        ffma2(acc[1][j], a1.y, b[j].y);
    }

    // Epilogue: fold even/odd partial sums, store
#pragma unroll
    for (int m = 0; m < 2; m++) {
#pragma unroll
        for (int j = 0; j < 4; j++) {
            if (n_idx[j] < REMAINED) {
                out[(size_t)(m0 + m) * REMAINED + n_idx[j]] = f32x2_hsum(acc[m][j]);
            }
        }
    }
}

extern "C" void kernel_launch(void* const* d_in, const int* in_sizes, int n_in,
                              void* d_out, int out_size) {
    const float* x   = (const float*)d_in[0];   // [32, 1, 4096] fp32
    const float* w   = (const float*)d_in[1];   // [11008, 4096] fp32
    const int*   idx = (const int*)d_in[2];     // [4403] int32
    float*       out = (float*)d_out;           // [32, 1, 4403] fp32

    const int grid = (REMAINED + TILE_N - 1) / TILE_N;  // 138
    sparse_rowgather_gemm<<<grid, THREADS>>>(x, w, idx, out);
}

// round 2
// speedup vs baseline: 4.7349x; 4.7349x over previous
#include <cuda_runtime.h>

#define D_FF     11008
#define D_MODEL  4096
#define REMAINED 4403
#define BATCH    32

#define BM       32            // all batches
#define BN       64            // gathered rows per block
#define BK       32            // k-tile
#define SPLITK   2
#define KSPLIT   (D_MODEL / SPLITK)   // 2048
#define NTILES   (KSPLIT / BK)        // 64
#define STRIDE   36            // smem row stride (floats), padded: conflict-free LDS.128
#define THREADS  256

#define OUT_ELEMS (BATCH * REMAINED)

// Packed fp32x2 FMA (Blackwell)
__device__ __forceinline__ void ffma2(unsigned long long& acc,
                                      unsigned long long a,
                                      unsigned long long b) {
    asm("fma.rn.f32x2 %0, %1, %2, %0;" : "+l"(acc) : "l"(a), "l"(b));
}

__device__ __forceinline__ float f32x2_hsum(unsigned long long v) {
    unsigned int lo, hi;
    asm("mov.b64 {%0, %1}, %2;" : "=r"(lo), "=r"(hi) : "l"(v));
    return __uint_as_float(lo) + __uint_as_float(hi);
}

__global__ void zero_out_kernel(float* __restrict__ out) {
    int i = blockIdx.x * blockDim.x + threadIdx.x;
    if (i < OUT_ELEMS) out[i] = 0.0f;
}

__global__ void __launch_bounds__(THREADS, 1)
sparse_rowgather_gemm(const float* __restrict__ x,      // [32, 4096]
                      const float* __restrict__ w,      // [11008, 4096]
                      const int*   __restrict__ idx,    // [4403]
                      float*       __restrict__ out)    // [32, 4403]
{
    __shared__ float xs[BM][STRIDE];   // 32 x 36
    __shared__ float ws[BN][STRIDE];   // 64 x 36

    const int tid   = threadIdx.x;
    const int nbase = blockIdx.x * BN;
    const int k0    = blockIdx.y * KSPLIT;

    // ---- fill roles ----
    const int fq  = tid & 7;          // quad within k-tile (0..7)
    const int fr  = tid >> 3;         // 0..31
    // x fill: batch row fr, quad fq
    const float* x_src = x + (size_t)fr * D_MODEL + k0 + fq * 4;
    // w fill: gathered rows fr and fr+32, quad fq
    int gn0 = nbase + fr;        if (gn0 >= REMAINED) gn0 = REMAINED - 1;
    int gn1 = nbase + fr + 32;   if (gn1 >= REMAINED) gn1 = REMAINED - 1;
    const float* w_src0 = w + (size_t)__ldg(&idx[gn0]) * D_MODEL + k0 + fq * 4;
    const float* w_src1 = w + (size_t)__ldg(&idx[gn1]) * D_MODEL + k0 + fq * 4;

    // ---- compute roles ----
    const int tx = tid & 15;          // row group: rows tx + 16j, j=0..3
    const int ty = tid >> 4;          // batch group: batches ty + 16m, m=0..1

    unsigned long long acc[2][4];
#pragma unroll
    for (int m = 0; m < 2; m++)
#pragma unroll
        for (int j = 0; j < 4; j++) acc[m][j] = 0ull;

    // prefetch tile 0 into registers
    float4 xa  = *(const float4*)(x_src);
    float4 wa0 = *(const float4*)(w_src0);
    float4 wa1 = *(const float4*)(w_src1);

    for (int t = 0; t < NTILES; t++) {
        __syncthreads();   // previous tile's compute done before overwrite
        *(float4*)&xs[fr][fq * 4]      = xa;
        *(float4*)&ws[fr][fq * 4]      = wa0;
        *(float4*)&ws[fr + 32][fq * 4] = wa1;
        __syncthreads();

        if (t + 1 < NTILES) {          // issue next tile's loads early
            const int koff = (t + 1) * BK;
            xa  = *(const float4*)(x_src  + koff);
            wa0 = *(const float4*)(w_src0 + koff);
            wa1 = *(const float4*)(w_src1 + koff);
        }

        // compute 8 quads (BK=32 -> 8 x float4)
#pragma unroll
        for (int kq = 0; kq < 8; kq++) {
            ulonglong2 xv[2], wv[4];
#pragma unroll
            for (int m = 0; m < 2; m++)
                xv[m] = *(const ulonglong2*)&xs[ty + 16 * m][kq * 4];
#pragma unroll
            for (int j = 0; j < 4; j++)
                wv[j] = *(const ulonglong2*)&ws[tx + 16 * j][kq * 4];

#pragma unroll
            for (int m = 0; m < 2; m++)
#pragma unroll
                for (int j = 0; j < 4; j++) {
                    ffma2(acc[m][j], xv[m].x, wv[j].x);
                    ffma2(acc[m][j], xv[m].y, wv[j].y);
                }
        }
    }

    // epilogue: fold packed partial sums, accumulate across the 2 K-splits
#pragma unroll
    for (int m = 0; m < 2; m++) {
        const int b = ty + 16 * m;
#pragma unroll
        for (int j = 0; j < 4; j++) {
            const int n = nbase + tx + 16 * j;
            if (n < REMAINED) {
                atomicAdd(&out[(size_t)b * REMAINED + n], f32x2_hsum(acc[m][j]));
            }
        }
    }
}

extern "C" void kernel_launch(void* const* d_in, const int* in_sizes, int n_in,
                              void* d_out, int out_size) {
    const float* x   = (const float*)d_in[0];   // [32, 1, 4096] fp32
    const float* w   = (const float*)d_in[1];   // [11008, 4096] fp32
    const int*   idx = (const int*)d_in[2];     // [4403] int32
    float*       out = (float*)d_out;           // [32, 1, 4403] fp32

    zero_out_kernel<<<(OUT_ELEMS + 511) / 512, 512>>>(out);

    dim3 grid((REMAINED + BN - 1) / BN, SPLITK);   // 69 x 2 = 138 blocks
    sparse_rowgather_gemm<<<grid, THREADS>>>(x, w, idx, out);
}

// round 3
// speedup vs baseline: 6.6408x; 1.4025x over previous
#include <cuda_runtime.h>

#define D_FF     11008
#define D_MODEL  4096
#define REMAINED 4403
#define BATCH    32

#define SPLITK   16
#define KCHUNK   (D_MODEL / SPLITK)      // 256
#define THREADS  256
#define NPB      512                      // n rows per block (2 per thread)
#define NBLK     ((REMAINED + NPB - 1) / NPB)   // 9
#define XSTRIDE  36                       // padded floats per xsT row (144B, 16B-aligned)

#define OUT_ELEMS (BATCH * REMAINED)

// split-K scratch: [SPLITK][BATCH*REMAINED]
__device__ float g_scratch[SPLITK * OUT_ELEMS];

// Packed fp32x2 FMA (Blackwell, PTX-only)
__device__ __forceinline__ void ffma2(unsigned long long& acc,
                                      unsigned long long a,
                                      unsigned long long b) {
    asm("fma.rn.f32x2 %0, %1, %2, %0;" : "+l"(acc) : "l"(a), "l"(b));
}
// splat one float into both f32x2 lanes
__device__ __forceinline__ unsigned long long splat2(float v) {
    unsigned long long r;
    asm("mov.b64 %0, {%1, %1};" : "=l"(r) : "r"(__float_as_uint(v)));
    return r;
}

__global__ void __launch_bounds__(THREADS, 1)
sparse_rowgather_gemm(const float* __restrict__ x,      // [32, 4096]
                      const float* __restrict__ w,      // [11008, 4096]
                      const int*   __restrict__ idx)    // [4403]
{
    __shared__ float xsT[KCHUNK][XSTRIDE];   // x transposed: xsT[k][m], 36KB

    const int tid   = threadIdx.x;
    const int nbase = blockIdx.x * NPB;
    const int k0    = blockIdx.y * KCHUNK;

    // ---- this thread's two gathered rows (interleaved for coalesced STG) ----
    const int n_a = nbase + tid;              // always < REMAINED (nbase<=4096, tid<=255)
    const int n_b = nbase + THREADS + tid;
    const bool b_ok = (n_b < REMAINED);
    const int r0 = idx[n_a];
    const int r1 = b_ok ? idx[n_b] : 0;
    const float4* wp0 = (const float4*)(w + (size_t)r0 * D_MODEL + k0);
    const float4* wp1 = (const float4*)(w + (size_t)r1 * D_MODEL + k0);

    // ---- cooperative transpose-load of x[k0..k0+255] into xsT ----
    {
        const int m = tid >> 3;          // batch row 0..31
        const int t = tid & 7;           // k sub-chunk
#pragma unroll
        for (int it = 0; it < 8; it++) {
            const int kk = t * 4 + it * 32;            // 0..255
            float4 v = *(const float4*)(x + (size_t)m * D_MODEL + k0 + kk);
            xsT[kk + 0][m] = v.x;
            xsT[kk + 1][m] = v.y;
            xsT[kk + 2][m] = v.z;
            xsT[kk + 3][m] = v.w;
        }
    }
    __syncthreads();

    // ---- accumulators: acc[q] packs batches (2q, 2q+1) ----
    unsigned long long acc0[16], acc1[16];
#pragma unroll
    for (int q = 0; q < 16; q++) { acc0[q] = 0ull; acc1[q] = 0ull; }

    const int NQ = KCHUNK / 4;           // 64 k-quads
    float4 wa0 = wp0[0];
    float4 wa1 = wp1[0];

#pragma unroll 1
    for (int kq = 0; kq < NQ; kq++) {
        float4 nw0, nw1;
        if (kq + 1 < NQ) { nw0 = wp0[kq + 1]; nw1 = wp1[kq + 1]; }

        const float wj0[4] = { wa0.x, wa0.y, wa0.z, wa0.w };
        const float wj1[4] = { wa1.x, wa1.y, wa1.z, wa1.w };
#pragma unroll
        for (int j = 0; j < 4; j++) {
            const int k = kq * 4 + j;
            const unsigned long long b0 = splat2(wj0[j]);
            const unsigned long long b1 = splat2(wj1[j]);
            const ulonglong2* xr = (const ulonglong2*)&xsT[k][0];
#pragma unroll
            for (int p = 0; p < 8; p++) {
                ulonglong2 xv = xr[p];               // broadcast LDS.128 (1 wf)
                ffma2(acc0[2 * p + 0], xv.x, b0);
                ffma2(acc0[2 * p + 1], xv.y, b0);
                ffma2(acc1[2 * p + 0], xv.x, b1);
                ffma2(acc1[2 * p + 1], xv.y, b1);
            }
        }
        wa0 = nw0; wa1 = nw1;
    }

    // ---- epilogue: scatter packed partial sums to this split's scratch ----
    float* scr = g_scratch + (size_t)blockIdx.y * OUT_ELEMS;
#pragma unroll
    for (int q = 0; q < 16; q++) {
        unsigned int lo, hi;
        asm("mov.b64 {%0, %1}, %2;" : "=r"(lo), "=r"(hi) : "l"(acc0[q]));
        scr[(size_t)(2 * q + 0) * REMAINED + n_a] = __uint_as_float(lo);
        scr[(size_t)(2 * q + 1) * REMAINED + n_a] = __uint_as_float(hi);
        if (b_ok) {
            asm("mov.b64 {%0, %1}, %2;" : "=r"(lo), "=r"(hi) : "l"(acc1[q]));
            scr[(size_t)(2 * q + 0) * REMAINED + n_b] = __uint_as_float(lo);
            scr[(size_t)(2 * q + 1) * REMAINED + n_b] = __uint_as_float(hi);
        }
    }
}

// deterministic split-K reduction (fixed order)
__global__ void reduce_splits(float* __restrict__ out) {
    int e = blockIdx.x * blockDim.x + threadIdx.x;
    if (e >= OUT_ELEMS) return;
    float s = 0.0f;
#pragma unroll
    for (int sp = 0; sp < SPLITK; sp++)
        s += g_scratch[(size_t)sp * OUT_ELEMS + e];
    out[e] = s;
}

extern "C" void kernel_launch(void* const* d_in, const int* in_sizes, int n_in,
                              void* d_out, int out_size) {
    const float* x   = (const float*)d_in[0];   // [32, 1, 4096] fp32
    const float* w   = (const float*)d_in[1];   // [11008, 4096] fp32
    const int*   idx = (const int*)d_in[2];     // [4403] int32
    float*       out = (float*)d_out;           // [32, 1, 4403] fp32

    dim3 grid(NBLK, SPLITK);                    // 9 x 16 = 144 blocks (one wave)
    sparse_rowgather_gemm<<<grid, THREADS>>>(x, w, idx);
    reduce_splits<<<(OUT_ELEMS + 255) / 256, 256>>>(out);
}

// round 4
// speedup vs baseline: 6.6781x; 1.0056x over previous
#include <cuda_runtime.h>

#define D_FF     11008
#define D_MODEL  4096
#define REMAINED 4403
#define BATCH    32

#define SPLITK   32
#define KCHUNK   (D_MODEL / SPLITK)      // 128
#define THREADS  256
#define NPB      512                     // rows per block (2 per thread)
#define NBLK     ((REMAINED + NPB - 1) / NPB)   // 9  -> grid 9 x 32 = 288 CTAs
#define XSTRIDE  36                      // padded floats per xsT row (144B, 16B aligned)

#define OUT_ELEMS (BATCH * REMAINED)     // 140,896 (divisible by 4)

// split-K scratch: [SPLITK][BATCH*REMAINED]  (~18 MB)
__device__ float g_scratch[(size_t)SPLITK * OUT_ELEMS];

// Packed fp32x2 FMA (Blackwell, PTX-only)
__device__ __forceinline__ void ffma2(unsigned long long& acc,
                                      unsigned long long a,
                                      unsigned long long b) {
    asm("fma.rn.f32x2 %0, %1, %2, %0;" : "+l"(acc) : "l"(a), "l"(b));
}
__device__ __forceinline__ unsigned long long splat2(float v) {
    unsigned long long r;
    asm("mov.b64 %0, {%1, %1};" : "=l"(r) : "r"(__float_as_uint(v)));
    return r;
}

__global__ void __launch_bounds__(THREADS, 2)
sparse_rowgather_gemm(const float* __restrict__ x,      // [32, 4096]
                      const float* __restrict__ w,      // [11008, 4096]
                      const int*   __restrict__ idx)    // [4403]
{
    __shared__ float xsT[KCHUNK][XSTRIDE];   // x transposed: xsT[k][m], 18KB

    const int tid   = threadIdx.x;
    const int nbase = blockIdx.x * NPB;
    const int k0    = blockIdx.y * KCHUNK;

    // ---- this thread's two gathered rows ----
    const int n_a = nbase + tid;                  // < 4608; nbase<=4096 so n_a<=4351 < REMAINED
    const int n_b = nbase + THREADS + tid;
    const bool b_ok = (n_b < REMAINED);
    const int r0 = idx[n_a];
    const int r1 = b_ok ? idx[n_b] : 0;
    const float4* wp0 = (const float4*)(w + (size_t)r0 * D_MODEL + k0);
    const float4* wp1 = (const float4*)(w + (size_t)r1 * D_MODEL + k0);

    // ---- cooperative transpose-load of x[:, k0..k0+127] into xsT ----
    {
        const int m = tid >> 3;          // batch row 0..31
        const int t = tid & 7;           // k sub-chunk
#pragma unroll
        for (int it = 0; it < 4; it++) {
            const int kk = t * 4 + it * 32;            // 0..127
            float4 v = *(const float4*)(x + (size_t)m * D_MODEL + k0 + kk);
            xsT[kk + 0][m] = v.x;
            xsT[kk + 1][m] = v.y;
            xsT[kk + 2][m] = v.z;
            xsT[kk + 3][m] = v.w;
        }
    }
    __syncthreads();

    // ---- accumulators: accR[q] packs batches (2q, 2q+1) for row R ----
    unsigned long long acc0[16], acc1[16];
#pragma unroll
    for (int q = 0; q < 16; q++) { acc0[q] = 0ull; acc1[q] = 0ull; }

    const int NQ = KCHUNK / 4;           // 32 k-quads
    float4 wa0 = wp0[0];
    float4 wa1 = wp1[0];

#pragma unroll 1
    for (int kq = 0; kq < NQ; kq++) {
        float4 nw0, nw1;
        if (kq + 1 < NQ) { nw0 = wp0[kq + 1]; nw1 = wp1[kq + 1]; }

        const float wj0[4] = { wa0.x, wa0.y, wa0.z, wa0.w };
        const float wj1[4] = { wa1.x, wa1.y, wa1.z, wa1.w };
#pragma unroll
        for (int j = 0; j < 4; j++) {
            const int k = kq * 4 + j;
            const unsigned long long b0 = splat2(wj0[j]);
            const unsigned long long b1 = splat2(wj1[j]);
            const ulonglong2* xr = (const ulonglong2*)&xsT[k][0];
#pragma unroll
            for (int p = 0; p < 8; p++) {
                ulonglong2 xv = xr[p];               // warp-broadcast LDS.128
                ffma2(acc0[2 * p + 0], xv.x, b0);
                ffma2(acc0[2 * p + 1], xv.y, b0);
                ffma2(acc1[2 * p + 0], xv.x, b1);
                ffma2(acc1[2 * p + 1], xv.y, b1);
            }
        }
        wa0 = nw0; wa1 = nw1;
    }

    // ---- epilogue: scatter packed partial sums to this split's scratch ----
    float* scr = g_scratch + (size_t)blockIdx.y * OUT_ELEMS;
#pragma unroll
    for (int q = 0; q < 16; q++) {
        unsigned int lo, hi;
        asm("mov.b64 {%0, %1}, %2;" : "=r"(lo), "=r"(hi) : "l"(acc0[q]));
        scr[(size_t)(2 * q + 0) * REMAINED + n_a] = __uint_as_float(lo);
        scr[(size_t)(2 * q + 1) * REMAINED + n_a] = __uint_as_float(hi);
        if (b_ok) {
            asm("mov.b64 {%0, %1}, %2;" : "=r"(lo), "=r"(hi) : "l"(acc1[q]));
            scr[(size_t)(2 * q + 0) * REMAINED + n_b] = __uint_as_float(lo);
            scr[(size_t)(2 * q + 1) * REMAINED + n_b] = __uint_as_float(hi);
        }
    }
}

// deterministic vectorized split-K reduction (fixed order, float4 lanes)
__global__ void reduce_splits(float* __restrict__ out) {
    const int e4 = blockIdx.x * blockDim.x + threadIdx.x;   // float4 index
    if (e4 >= OUT_ELEMS / 4) return;
    const float4* src = (const float4*)g_scratch;
    float4 s = make_float4(0.f, 0.f, 0.f, 0.f);
#pragma unroll
    for (int sp = 0; sp < SPLITK; sp++) {
        float4 v = src[(size_t)sp * (OUT_ELEMS / 4) + e4];
        s.x += v.x; s.y += v.y; s.z += v.z; s.w += v.w;
    }
    ((float4*)out)[e4] = s;
}

extern "C" void kernel_launch(void* const* d_in, const int* in_sizes, int n_in,
                              void* d_out, int out_size) {
    const float* x   = (const float*)d_in[0];   // [32, 1, 4096] fp32
    const float* w   = (const float*)d_in[1];   // [11008, 4096] fp32
    const int*   idx = (const int*)d_in[2];     // [4403] int32
    float*       out = (float*)d_out;           // [32, 1, 4403] fp32

    dim3 grid(NBLK, SPLITK);                    // 9 x 32 = 288 CTAs (one wave @ 2/SM)
    sparse_rowgather_gemm<<<grid, THREADS>>>(x, w, idx);
    reduce_splits<<<(OUT_ELEMS / 4 + 255) / 256, 256>>>(out);
}

// round 7
// speedup vs baseline: 7.2431x; 1.0846x over previous
#include <cuda_runtime.h>
#include <cstdint>

#define D_MODEL  4096
#define REMAINED 4403
#define BATCH    32

#define SPLITK   4
#define KSPLIT   (D_MODEL / SPLITK)     // 1024
#define KC       64                     // k per chunk
#define NCHUNK   (KSPLIT / KC)          // 16
#define MTILE    128
#define NBLKM    ((REMAINED + MTILE - 1) / MTILE)   // 35
#define THREADS  256

#define OUT_ELEMS (BATCH * REMAINED)    // 140896

// smem: padded rows of 72 bf16 (144 B) -> conflict-free ldmatrix/STS
#define RSTR     72                     // bf16 elements per row (stride)
#define RSTRB    (RSTR * 2)             // 144 bytes
#define SM_WHI   0
#define SM_WLO   (SM_WHI + MTILE * RSTRB)   // 18432
#define SM_XHI   (SM_WLO + MTILE * RSTRB)   // 36864
#define SM_XLO   (SM_XHI + BATCH * RSTRB)   // 41472
#define SM_TOTAL (SM_XLO + BATCH * RSTRB)   // 46080 (< 48KB static)

__device__ float g_scratch[(size_t)SPLITK * OUT_ELEMS];   // ~2.25 MB

// ---------------- helpers ----------------
__device__ __forceinline__ uint32_t smem_u32(const void* p) {
    uint32_t a;
    asm("{ .reg .u64 t; cvta.to.shared.u64 t, %1; cvt.u32.u64 %0, t; }" : "=r"(a) : "l"(p));
    return a;
}
// pack top-16-bits (bf16 truncation) of two floats: result = {hi16(a) lo-half, hi16(b) hi-half}
__device__ __forceinline__ uint32_t pack_hi(float a, float b) {
    uint32_t r;
    asm("prmt.b32 %0, %1, %2, 0x7632;" : "=r"(r)
        : "r"(__float_as_uint(a)), "r"(__float_as_uint(b)));
    return r;
}
__device__ __forceinline__ float hi_f(float v) {
    return __uint_as_float(__float_as_uint(v) & 0xFFFF0000u);
}
// pack two floats to bf16x2 (round-nearest): lane0 = lo arg, lane1 = hi arg
__device__ __forceinline__ uint32_t pack_lo(float e0, float e1) {
    uint32_t r;
    asm("cvt.rn.bf16x2.f32 %0, %1, %2;" : "=r"(r) : "f"(e1), "f"(e0));
    return r;
}
__device__ __forceinline__ void ldm_x4(uint32_t* r, uint32_t addr) {
    asm volatile("ldmatrix.sync.aligned.m8n8.x4.shared.b16 {%0,%1,%2,%3}, [%4];"
        : "=r"(r[0]), "=r"(r[1]), "=r"(r[2]), "=r"(r[3]) : "r"(addr));
}
__device__ __forceinline__ void mma_bf16(float* c, const uint32_t* a, const uint32_t* b) {
    asm volatile("mma.sync.aligned.m16n8k16.row.col.f32.bf16.bf16.f32 "
        "{%0,%1,%2,%3}, {%4,%5,%6,%7}, {%8,%9}, {%0,%1,%2,%3};"
        : "+f"(c[0]), "+f"(c[1]), "+f"(c[2]), "+f"(c[3])
        : "r"(a[0]), "r"(a[1]), "r"(a[2]), "r"(a[3]), "r"(b[0]), "r"(b[1]));
}

// convert one float4 to hi/lo bf16x2 pairs and store 8B each
__device__ __forceinline__ void split_store(char* base_hi, char* base_lo,
                                            uint32_t off, float4 v) {
    uint32_t h0 = pack_hi(v.x, v.y);
    uint32_t h1 = pack_hi(v.z, v.w);
    float l0 = v.x - hi_f(v.x), l1 = v.y - hi_f(v.y);
    float l2 = v.z - hi_f(v.z), l3 = v.w - hi_f(v.w);
    uint32_t e0 = pack_lo(l0, l1);
    uint32_t e1 = pack_lo(l2, l3);
    *(uint2*)(base_hi + off) = make_uint2(h0, h1);
    *(uint2*)(base_lo + off) = make_uint2(e0, e1);
}

// ---------------- main GEMM ----------------
__global__ void __launch_bounds__(THREADS, 1)
gemm_bf16x3(const float* __restrict__ x,      // [32, 4096]
            const float* __restrict__ w,      // [11008, 4096]
            const int*   __restrict__ idx)    // [4403]
{
    __shared__ __align__(16) char smem[SM_TOTAL];
    const uint32_t sb = smem_u32(smem);

    const int tid   = threadIdx.x;
    const int lane  = tid & 31;
    const int wq    = tid >> 5;           // warp 0..7
    const int mg    = wq >> 1;            // m-group 0..3 (32 rows each)
    const int ng    = wq & 1;             // n-group 0..1 (16 batch each)
    const int mbase = blockIdx.x * MTILE;
    const int k0    = blockIdx.y * KSPLIT;

    // ---- load geometry ----
    const int wrow = tid >> 1;            // 0..127
    const int wseg = (tid & 1) * 32;      // k offset 0 / 32
    int gn = mbase + wrow; if (gn >= REMAINED) gn = REMAINED - 1;
    const float4* wp = (const float4*)(w + (size_t)idx[gn] * D_MODEL + k0 + wseg);
    const int xrow = tid & 31;
    const int xseg = (tid >> 5) * 8;      // 0..56
    const float4* xp = (const float4*)(x + (size_t)xrow * D_MODEL + k0 + xseg);

    const uint32_t w_sts = (uint32_t)(wrow * RSTRB + wseg * 2);
    const uint32_t x_sts = (uint32_t)(xrow * RSTRB + xseg * 2);

    // ---- ldmatrix addresses (chunk-invariant base parts) ----
    // A (m16k16): row = mg*32 + s*16 + lane%16, khalf = lane/16
    const uint32_t a_row = (uint32_t)(mg * 32 + (lane & 15));
    const uint32_t a_off = a_row * RSTRB + (lane >> 4) * 16;       // +s*16*RSTRB +kstep*32
    // B x4 (n16k16): n = ng*16 + lane%8 + (lane/16)*8, khalf = (lane>>3)&1
    const uint32_t b_row = (uint32_t)(ng * 16 + (lane & 7) + ((lane >> 4) << 3));
    const uint32_t b_off = b_row * RSTRB + ((lane >> 3) & 1) * 16; // +kstep*32

    float acc[2][2][4];
#pragma unroll
    for (int s = 0; s < 2; s++)
#pragma unroll
        for (int n = 0; n < 2; n++)
#pragma unroll
            for (int r = 0; r < 4; r++) acc[s][n][r] = 0.f;

    // prefetch chunk 0
    float4 pw[8], px[2];
#pragma unroll
    for (int i = 0; i < 8; i++) pw[i] = wp[i];
#pragma unroll
    for (int i = 0; i < 2; i++) px[i] = xp[i];

#pragma unroll 1
    for (int c = 0; c < NCHUNK; c++) {
        __syncthreads();   // consumers done with previous chunk's smem

        // split + store chunk c
#pragma unroll
        for (int i = 0; i < 8; i++)
            split_store(smem + SM_WHI, smem + SM_WLO, w_sts + i * 8, pw[i]);
#pragma unroll
        for (int i = 0; i < 2; i++)
            split_store(smem + SM_XHI, smem + SM_XLO, x_sts + i * 8, px[i]);
        __syncthreads();

        // issue next chunk's gmem loads (hidden under MMA below)
        if (c + 1 < NCHUNK) {
            const int o4 = (c + 1) * (KC / 4);
#pragma unroll
            for (int i = 0; i < 8; i++) pw[i] = wp[o4 + i];
#pragma unroll
            for (int i = 0; i < 2; i++) px[i] = xp[o4 + i];
        }

        // compute: 4 k-steps of 16
#pragma unroll
        for (int ks = 0; ks < 4; ks++) {
            const uint32_t ka = (uint32_t)(ks * 32);
            uint32_t ahi[2][4], alo[2][4], bhi[4], blo[4];
#pragma unroll
            for (int s = 0; s < 2; s++) {
                uint32_t ao = a_off + (uint32_t)(s * 16 * RSTRB) + ka;
                ldm_x4(ahi[s], sb + SM_WHI + ao);
                ldm_x4(alo[s], sb + SM_WLO + ao);
            }
            ldm_x4(bhi, sb + SM_XHI + b_off + ka);
            ldm_x4(blo, sb + SM_XLO + b_off + ka);

#pragma unroll
            for (int s = 0; s < 2; s++)
#pragma unroll
                for (int n = 0; n < 2; n++) {
                    mma_bf16(acc[s][n], ahi[s], bhi + 2 * n);   // hi*hi
                    mma_bf16(acc[s][n], ahi[s], blo + 2 * n);   // hi*lo
                    mma_bf16(acc[s][n], alo[s], bhi + 2 * n);   // lo*hi
                }
        }
    }

    // ---- epilogue: C fragment scatter to split scratch ----
    float* scr = g_scratch + (size_t)blockIdx.y * OUT_ELEMS;
#pragma unroll
    for (int s = 0; s < 2; s++) {
        const int n_row0 = mbase + mg * 32 + s * 16 + (lane >> 2);
#pragma unroll
        for (int n = 0; n < 2; n++) {
            const int b0 = ng * 16 + n * 8 + 2 * (lane & 3);
            if (n_row0 < REMAINED) {
                scr[(size_t)(b0 + 0) * REMAINED + n_row0] = acc[s][n][0];
                scr[(size_t)(b0 + 1) * REMAINED + n_row0] = acc[s][n][1];
            }
            if (n_row0 + 8 < REMAINED) {
                scr[(size_t)(b0 + 0) * REMAINED + n_row0 + 8] = acc[s][n][2];
                scr[(size_t)(b0 + 1) * REMAINED + n_row0 + 8] = acc[s][n][3];
            }
        }
    }
}

// ---------------- deterministic split-K reduce ----------------
__global__ void reduce_splits(float* __restrict__ out) {
    const int e4 = blockIdx.x * blockDim.x + threadIdx.x;
    if (e4 >= OUT_ELEMS / 4) return;
    const float4* src = (const float4*)g_scratch;
    float4 s = make_float4(0.f, 0.f, 0.f, 0.f);
#pragma unroll
    for (int sp = 0; sp < SPLITK; sp++) {
        float4 v = src[(size_t)sp * (OUT_ELEMS / 4) + e4];
        s.x += v.x; s.y += v.y; s.z += v.z; s.w += v.w;
    }
    ((float4*)out)[e4] = s;
}

extern "C" void kernel_launch(void* const* d_in, const int* in_sizes, int n_in,
                              void* d_out, int out_size) {
    const float* x   = (const float*)d_in[0];
    const float* w   = (const float*)d_in[1];
    const int*   idx = (const int*)d_in[2];
    float*       out = (float*)d_out;

    dim3 grid(NBLKM, SPLITK);               // 35 x 4 = 140 CTAs (1/SM)
    gemm_bf16x3<<<grid, THREADS>>>(x, w, idx);
    reduce_splits<<<(OUT_ELEMS / 4 + 255) / 256, 256>>>(out);
}